// round 1
// baseline (speedup 1.0000x reference)
#include <cuda_runtime.h>
#include <math.h>

// Problem shape (fixed by the dataset)
#define Bq  4
#define Sq  2048
#define Dq  1024
#define Hq  16
#define HDq 64
#define Mrows (Bq*Sq)          // 8192

// ---------------------------------------------------------------------------
// Scratch (device globals: allocation-free per harness rules)
// ---------------------------------------------------------------------------
__device__ float g_qkv [(size_t)Mrows * 3 * Dq];     // 8192 x 3072
__device__ float g_q   [(size_t)Bq*Hq*Sq*HDq];       // [b,h,s,d]
__device__ float g_k   [(size_t)Bq*Hq*Sq*HDq];
__device__ float g_v   [(size_t)Bq*Hq*Sq*HDq];
__device__ float g_attn[(size_t)Mrows * Dq];         // [b,s,D] attention output

// ---------------------------------------------------------------------------
// SGEMM: C[M,N] = A[M,K] @ B[K,N], row-major, all dims multiples of tiles.
// 128x128 block tile, BK=16, 256 threads, 8x8 per thread.
// ---------------------------------------------------------------------------
#define GBM 128
#define GBN 128
#define GBK 16
#define GTM 8
#define GTN 8

__global__ __launch_bounds__(256) void sgemm_kernel(
    const float* __restrict__ A, const float* __restrict__ B,
    float* __restrict__ C, int M, int N, int K)
{
    __shared__ float As[GBK][GBM];
    __shared__ float Bs[GBK][GBN];

    const int tid  = threadIdx.x;
    const int row0 = blockIdx.y * GBM;
    const int col0 = blockIdx.x * GBN;
    const int tx   = tid & 15;   // 0..15 -> 8 cols each
    const int ty   = tid >> 4;   // 0..15 -> 8 rows each

    float acc[GTM][GTN];
    #pragma unroll
    for (int i = 0; i < GTM; i++)
        #pragma unroll
        for (int j = 0; j < GTN; j++) acc[i][j] = 0.f;

    const float* Aptr = A + (size_t)row0 * K;
    const float* Bptr = B + col0;

    for (int kk = 0; kk < K; kk += GBK) {
        // Load A tile (128x16) as float4, store transposed into As[k][m]
        #pragma unroll
        for (int i = 0; i < 2; i++) {
            int f  = tid + i * 256;       // 0..511 float4 slots
            int r  = f >> 2;              // 0..127
            int c4 = f & 3;               // 0..3
            float4 v = *(const float4*)(Aptr + (size_t)r * K + kk + c4 * 4);
            As[c4*4+0][r] = v.x;
            As[c4*4+1][r] = v.y;
            As[c4*4+2][r] = v.z;
            As[c4*4+3][r] = v.w;
        }
        // Load B tile (16x128) as float4
        #pragma unroll
        for (int i = 0; i < 2; i++) {
            int f  = tid + i * 256;
            int r  = f >> 5;              // 0..15
            int c4 = f & 31;              // 0..31
            *(float4*)(&Bs[r][c4*4]) =
                *(const float4*)(Bptr + (size_t)(kk + r) * N + c4 * 4);
        }
        __syncthreads();

        #pragma unroll
        for (int k = 0; k < GBK; k++) {
            float ra[GTM], rb[GTN];
            #pragma unroll
            for (int i = 0; i < GTM; i++) ra[i] = As[k][ty*GTM + i];
            #pragma unroll
            for (int j = 0; j < GTN; j++) rb[j] = Bs[k][tx*GTN + j];
            #pragma unroll
            for (int i = 0; i < GTM; i++)
                #pragma unroll
                for (int j = 0; j < GTN; j++)
                    acc[i][j] += ra[i] * rb[j];
        }
        __syncthreads();
    }

    #pragma unroll
    for (int i = 0; i < GTM; i++) {
        int r = row0 + ty*GTM + i;
        #pragma unroll
        for (int j = 0; j < GTN; j += 4) {
            float4 v = make_float4(acc[i][j], acc[i][j+1], acc[i][j+2], acc[i][j+3]);
            *(float4*)(C + (size_t)r * N + col0 + tx*GTN + j) = v;
        }
    }
}

// ---------------------------------------------------------------------------
// RoPE + head split + transpose: qkv[b,s,3D] -> q/k/v[b,h,s,HD]
// out[j]    = x[2j]*cos - x[2j+1]*sin     (j < 32)
// out[32+j] = x[2j]*sin + x[2j+1]*cos
// v is just reshaped/transposed.
// One thread per (b,h,s,j) pair, j in [0,32).
// ---------------------------------------------------------------------------
__global__ __launch_bounds__(256) void rope_kernel(
    const float* __restrict__ qkv,
    const float* __restrict__ cosp, const float* __restrict__ sinp,
    float* __restrict__ gq, float* __restrict__ gk, float* __restrict__ gv)
{
    int idx = blockIdx.x * blockDim.x + threadIdx.x;   // B*H*S*32 total
    int j = idx & 31;
    int h = (idx >> 5) & (Hq - 1);
    int s = (idx >> 9) & (Sq - 1);
    int b = idx >> 20;
    if (b >= Bq) return;

    const size_t src = ((size_t)(b * Sq + s)) * (3 * Dq) + h * HDq;
    float q0 = qkv[src + 2*j],          q1 = qkv[src + 2*j + 1];
    float k0 = qkv[src + Dq + 2*j],     k1 = qkv[src + Dq + 2*j + 1];
    float v0 = qkv[src + 2*Dq + 2*j],   v1 = qkv[src + 2*Dq + 2*j + 1];

    float c = cosp[s * 32 + j];
    float sn = sinp[s * 32 + j];

    const size_t dst = (((size_t)(b * Hq + h)) * Sq + s) * HDq;
    gq[dst + j]       = q0 * c  - q1 * sn;
    gq[dst + 32 + j]  = q0 * sn + q1 * c;
    gk[dst + j]       = k0 * c  - k1 * sn;
    gk[dst + 32 + j]  = k0 * sn + k1 * c;
    gv[dst + 2*j]     = v0;
    gv[dst + 2*j + 1] = v1;
}

// ---------------------------------------------------------------------------
// Causal flash attention. 1 thread = 1 query row. 128 queries / block.
// Key tile = 32. Online softmax in exp2 domain (scale*log2e folded into q).
// Mask input is causal with -1e9: exp underflows to exactly 0 in fp32, so
// causal skipping is bit-equivalent to adding the mask.
// Output written directly in [b,s,D] layout for the output projection.
// ---------------------------------------------------------------------------
#define AQ 128
#define AK 32

__global__ __launch_bounds__(128) void attn_kernel(
    const float* __restrict__ gq, const float* __restrict__ gk,
    const float* __restrict__ gv, float* __restrict__ gout)
{
    const int b   = blockIdx.z;
    const int h   = blockIdx.y;
    const int q0  = blockIdx.x * AQ;
    const int tid = threadIdx.x;
    const int qi  = q0 + tid;

    __shared__ float Qs[AQ][HDq + 1];   // +1 pad: conflict-free row reads
    __shared__ float Ks[AK][HDq];
    __shared__ float Vs[AK][HDq];

    const size_t head_base = ((size_t)(b * Hq + h)) * Sq * HDq;
    const float* qptr = gq + head_base;
    const float* kptr = gk + head_base;
    const float* vptr = gv + head_base;

    // Stage Q tile (coalesced), then pull own row into registers.
    for (int i = tid; i < AQ * (HDq / 4); i += 128) {
        int r  = i / (HDq / 4);
        int c4 = i % (HDq / 4);
        float4 v = *(const float4*)(qptr + (size_t)(q0 + r) * HDq + c4 * 4);
        Qs[r][c4*4+0] = v.x; Qs[r][c4*4+1] = v.y;
        Qs[r][c4*4+2] = v.z; Qs[r][c4*4+3] = v.w;
    }
    __syncthreads();

    const float sc = 0.125f * 1.4426950408889634f;  // 1/sqrt(64) * log2(e)
    float q[HDq];
    #pragma unroll
    for (int d = 0; d < HDq; d++) q[d] = Qs[tid][d] * sc;

    float m = -1e30f, l = 0.f;
    float acc[HDq];
    #pragma unroll
    for (int d = 0; d < HDq; d++) acc[d] = 0.f;

    const int ntiles = (q0 + AQ) / AK;
    for (int t = 0; t < ntiles; t++) {
        const int k0 = t * AK;
        __syncthreads();
        // Cooperative K/V tile load (coalesced float4)
        for (int i = tid; i < AK * (HDq / 4); i += 128) {
            int r  = i / (HDq / 4);
            int c4 = i % (HDq / 4);
            *(float4*)(&Ks[r][c4*4]) =
                *(const float4*)(kptr + (size_t)(k0 + r) * HDq + c4 * 4);
            *(float4*)(&Vs[r][c4*4]) =
                *(const float4*)(vptr + (size_t)(k0 + r) * HDq + c4 * 4);
        }
        __syncthreads();

        if (k0 > qi) continue;   // fully masked tile for this query

        float s[AK];
        float tmax = -1e30f;
        #pragma unroll
        for (int j = 0; j < AK; j++) {
            float sj = 0.f;
            #pragma unroll
            for (int d = 0; d < HDq; d++) sj += q[d] * Ks[j][d];
            sj = (k0 + j <= qi) ? sj : -1e30f;
            s[j] = sj;
            tmax = fmaxf(tmax, sj);
        }
        float mnew = fmaxf(m, tmax);
        float corr = exp2f(m - mnew);
        l *= corr;
        #pragma unroll
        for (int d = 0; d < HDq; d++) acc[d] *= corr;
        #pragma unroll
        for (int j = 0; j < AK; j++) {
            float p = exp2f(s[j] - mnew);
            l += p;
            #pragma unroll
            for (int d = 0; d < HDq; d++) acc[d] += p * Vs[j][d];
        }
        m = mnew;
    }

    const float inv = 1.f / l;
    float* optr = gout + ((size_t)b * Sq + qi) * Dq + h * HDq;
    #pragma unroll
    for (int d = 0; d < HDq; d += 4) {
        float4 v = make_float4(acc[d]*inv, acc[d+1]*inv, acc[d+2]*inv, acc[d+3]*inv);
        *(float4*)(optr + d) = v;
    }
}

// ---------------------------------------------------------------------------
// Launch
// ---------------------------------------------------------------------------
extern "C" void kernel_launch(void* const* d_in, const int* in_sizes, int n_in,
                              void* d_out, int out_size)
{
    const float* x    = (const float*)d_in[0];
    const float* cosp = (const float*)d_in[1];
    const float* sinp = (const float*)d_in[2];
    // d_in[3] = mask: causal, -1e9 fill — handled analytically, never read.
    const float* Wqkv = (const float*)d_in[4];
    const float* Wout = (const float*)d_in[5];
    float* out = (float*)d_out;

    float *p_qkv, *p_q, *p_k, *p_v, *p_attn;
    cudaGetSymbolAddress((void**)&p_qkv,  g_qkv);
    cudaGetSymbolAddress((void**)&p_q,    g_q);
    cudaGetSymbolAddress((void**)&p_k,    g_k);
    cudaGetSymbolAddress((void**)&p_v,    g_v);
    cudaGetSymbolAddress((void**)&p_attn, g_attn);

    // 1) QKV projection: [8192,1024] @ [1024,3072]
    {
        dim3 grid(3 * Dq / GBN, Mrows / GBM);
        sgemm_kernel<<<grid, 256>>>(x, Wqkv, p_qkv, Mrows, 3 * Dq, Dq);
    }
    // 2) RoPE + head transpose
    {
        int total = Bq * Hq * Sq * 32;
        rope_kernel<<<total / 256, 256>>>(p_qkv, cosp, sinp, p_q, p_k, p_v);
    }
    // 3) Causal flash attention
    {
        dim3 grid(Sq / AQ, Hq, Bq);
        attn_kernel<<<grid, 128>>>(p_q, p_k, p_v, p_attn);
    }
    // 4) Output projection: [8192,1024] @ [1024,1024]
    {
        dim3 grid(Dq / GBN, Mrows / GBM);
        sgemm_kernel<<<grid, 256>>>(p_attn, Wout, out, Mrows, Dq, Dq);
    }
}

// round 3
// speedup vs baseline: 1.3925x; 1.3925x over previous
#include <cuda_runtime.h>
#include <cuda_bf16.h>
#include <math.h>
#include <cstdint>

// Problem shape (fixed by the dataset)
#define Bq  4
#define Sq  2048
#define Dq  1024
#define Hq  16
#define HDq 64
#define Mrows (Bq*Sq)          // 8192
#define Kdim 1024

// ---------------------------------------------------------------------------
// Scratch (device globals: allocation-free per harness rules)
// ---------------------------------------------------------------------------
__device__ float g_qkv [(size_t)Mrows * 3 * Dq];     // 8192 x 3072
__device__ float g_q   [(size_t)Mrows * Dq];         // [b,h,s,d]
__device__ float g_k   [(size_t)Mrows * Dq];
__device__ float g_v   [(size_t)Mrows * Dq];
__device__ float g_attn[(size_t)Mrows * Dq];         // [b,s,D]

// split-bf16 operands
__device__ __nv_bfloat16 g_xhi [(size_t)Mrows * Kdim];
__device__ __nv_bfloat16 g_xlo [(size_t)Mrows * Kdim];
__device__ __nv_bfloat16 g_w1hi[(size_t)3 * Dq * Kdim];   // WqkvT [3072,1024]
__device__ __nv_bfloat16 g_w1lo[(size_t)3 * Dq * Kdim];
__device__ __nv_bfloat16 g_w2hi[(size_t)Dq * Kdim];       // WoutT [1024,1024]
__device__ __nv_bfloat16 g_w2lo[(size_t)Dq * Kdim];
__device__ __nv_bfloat16 g_ahi [(size_t)Mrows * Kdim];
__device__ __nv_bfloat16 g_alo [(size_t)Mrows * Kdim];

// ---------------------------------------------------------------------------
// PTX helpers (plain sm_80+/sm_90 features only — NO tcgen05: the bench
// toolchain lowers to .target sm_103 (no 'a'), which rejects arch-specific ops)
// ---------------------------------------------------------------------------
__device__ __forceinline__ uint32_t smem_u32(const void* p) {
    uint32_t a;
    asm("{ .reg .u64 t; cvta.to.shared.u64 t, %1; cvt.u32.u64 %0, t; }"
        : "=r"(a) : "l"(p));
    return a;
}
__device__ __forceinline__ void cp_async16(uint32_t s, const void* g) {
    asm volatile("cp.async.cg.shared.global [%0], [%1], 16;" :: "r"(s), "l"(g));
}
__device__ __forceinline__ void cp_commit() {
    asm volatile("cp.async.commit_group;" ::: "memory");
}
template<int N> __device__ __forceinline__ void cp_wait() {
    asm volatile("cp.async.wait_group %0;" :: "n"(N) : "memory");
}
__device__ __forceinline__ void ldmx4(uint32_t addr, uint32_t* r) {
    asm volatile("ldmatrix.sync.aligned.m8n8.x4.shared.b16 {%0,%1,%2,%3}, [%4];"
        : "=r"(r[0]), "=r"(r[1]), "=r"(r[2]), "=r"(r[3]) : "r"(addr));
}
__device__ __forceinline__ void mma16816(float* d, const uint32_t* a,
                                         uint32_t b0, uint32_t b1) {
    asm volatile(
        "mma.sync.aligned.m16n8k16.row.col.f32.bf16.bf16.f32 "
        "{%0,%1,%2,%3}, {%4,%5,%6,%7}, {%8,%9}, {%0,%1,%2,%3};"
        : "+f"(d[0]), "+f"(d[1]), "+f"(d[2]), "+f"(d[3])
        : "r"(a[0]), "r"(a[1]), "r"(a[2]), "r"(a[3]), "r"(b0), "r"(b1));
}

// ---------------------------------------------------------------------------
// Split-bf16 conversion: x -> (hi, lo)
// ---------------------------------------------------------------------------
__global__ __launch_bounds__(256) void split_kernel(
    const float* __restrict__ x, __nv_bfloat16* __restrict__ hi,
    __nv_bfloat16* __restrict__ lo, int n4)
{
    int i = blockIdx.x * blockDim.x + threadIdx.x;
    if (i >= n4) return;
    float4 v = ((const float4*)x)[i];
    __nv_bfloat16 h0 = __float2bfloat16(v.x);
    __nv_bfloat16 h1 = __float2bfloat16(v.y);
    __nv_bfloat16 h2 = __float2bfloat16(v.z);
    __nv_bfloat16 h3 = __float2bfloat16(v.w);
    __nv_bfloat16 l0 = __float2bfloat16(v.x - __bfloat162float(h0));
    __nv_bfloat16 l1 = __float2bfloat16(v.y - __bfloat162float(h1));
    __nv_bfloat16 l2 = __float2bfloat16(v.z - __bfloat162float(h2));
    __nv_bfloat16 l3 = __float2bfloat16(v.w - __bfloat162float(h3));
    ushort4 hv = make_ushort4(__bfloat16_as_ushort(h0), __bfloat16_as_ushort(h1),
                              __bfloat16_as_ushort(h2), __bfloat16_as_ushort(h3));
    ushort4 lv = make_ushort4(__bfloat16_as_ushort(l0), __bfloat16_as_ushort(l1),
                              __bfloat16_as_ushort(l2), __bfloat16_as_ushort(l3));
    ((ushort4*)hi)[i] = hv;
    ((ushort4*)lo)[i] = lv;
}

// ---------------------------------------------------------------------------
// Transpose + split: W[K,N] fp32 -> T[N,K] bf16 hi/lo
// ---------------------------------------------------------------------------
__global__ __launch_bounds__(256) void transpose_split_kernel(
    const float* __restrict__ W, __nv_bfloat16* __restrict__ Thi,
    __nv_bfloat16* __restrict__ Tlo, int K, int N)
{
    __shared__ float t[32][33];
    int n0 = blockIdx.x * 32, k0 = blockIdx.y * 32;
    int tx = threadIdx.x, ty = threadIdx.y;   // (32, 8)
    #pragma unroll
    for (int i = 0; i < 32; i += 8)
        t[ty + i][tx] = W[(size_t)(k0 + ty + i) * N + n0 + tx];
    __syncthreads();
    #pragma unroll
    for (int i = 0; i < 32; i += 8) {
        float v = t[tx][ty + i];
        __nv_bfloat16 h = __float2bfloat16(v);
        size_t o = (size_t)(n0 + ty + i) * K + k0 + tx;
        Thi[o] = h;
        Tlo[o] = __float2bfloat16(v - __bfloat162float(h));
    }
}

// ---------------------------------------------------------------------------
// mma.sync split-bf16 GEMM: C[M,N] = A[M,1024] @ B^T, B stored [N,1024].
// CTA 128x128, BK=32, 8 warps (warp tile 64x32), 3-stage cp.async pipeline.
// 3 MMA products (AhiBhi + AhiBlo + AloBhi) into one fp32 accumulator.
// SMEM layout per stage: 4 tiles (Ahi,Alo,Bhi,Blo) of [128 rows][32 k] bf16,
// 64B rows, 16B-chunk swizzle: chunk' = chunk ^ ((row>>1)&3).
// ---------------------------------------------------------------------------
#define NKT      (Kdim / 32)      // 32 k-tiles
#define TILE8K   8192             // one 128x32 bf16 tile
#define STAGE_B  (4 * TILE8K)     // 32 KB per stage
#define GEMM_SMEM (3 * STAGE_B)   // 96 KB

__global__ __launch_bounds__(256, 1) void gemm_mma(
    const __nv_bfloat16* __restrict__ Ahi, const __nv_bfloat16* __restrict__ Alo,
    const __nv_bfloat16* __restrict__ Bhi, const __nv_bfloat16* __restrict__ Blo,
    float* __restrict__ C, int N)
{
    extern __shared__ char sm[];
    const uint32_t sbase = smem_u32(sm);
    const int tid = threadIdx.x, wid = tid >> 5, lane = tid & 31;
    const int row0 = blockIdx.y * 128, col0 = blockIdx.x * 128;
    const int wm = (wid >> 2) * 64, wn = (wid & 3) * 32;

    const __nv_bfloat16* gsrc[4] = {
        Ahi + (size_t)row0 * Kdim, Alo + (size_t)row0 * Kdim,
        Bhi + (size_t)col0 * Kdim, Blo + (size_t)col0 * Kdim };

    float acc[4][4][4];
    #pragma unroll
    for (int i = 0; i < 4; i++)
        #pragma unroll
        for (int j = 0; j < 4; j++)
            #pragma unroll
            for (int r = 0; r < 4; r++) acc[i][j][r] = 0.f;

    const int lrow = tid >> 2;   // 0..63
    const int lch  = tid & 3;    // 16B chunk within 64B row

    auto LOAD = [&](int ct, int st) {
        const int kk = ct * 32;
        const uint32_t sb = sbase + st * STAGE_B;
        #pragma unroll
        for (int t = 0; t < 4; t++) {
            #pragma unroll
            for (int rep = 0; rep < 2; rep++) {
                int row = lrow + rep * 64;
                uint32_t so = sb + t * TILE8K + row * 64
                            + ((uint32_t)(lch ^ ((row >> 1) & 3)) << 4);
                cp_async16(so, gsrc[t] + (size_t)row * Kdim + kk + lch * 8);
            }
        }
        cp_commit();
    };

    auto COMPUTE = [&](int st) {
        const uint32_t Ah = sbase + st * STAGE_B;
        const uint32_t Al = Ah + TILE8K, Bh = Ah + 2 * TILE8K, Bl = Ah + 3 * TILE8K;
        const int g = lane >> 3, lr = lane & 7;
        #pragma unroll
        for (int s = 0; s < 2; s++) {          // two k16 steps per BK=32
            uint32_t af[4][4], alf[4][4], bf[2][4], blf[2][4];
            #pragma unroll
            for (int i = 0; i < 4; i++) {
                int row = wm + 16 * i + (g & 1) * 8 + lr;
                int ch  = 2 * s + (g >> 1);
                uint32_t off = (uint32_t)(row * 64
                              + ((ch ^ ((row >> 1) & 3)) << 4));
                ldmx4(Ah + off, af[i]);
                ldmx4(Al + off, alf[i]);
            }
            #pragma unroll
            for (int h = 0; h < 2; h++) {
                int row = wn + 16 * h + (g >> 1) * 8 + lr;
                int ch  = 2 * s + (g & 1);
                uint32_t off = (uint32_t)(row * 64
                              + ((ch ^ ((row >> 1) & 3)) << 4));
                ldmx4(Bh + off, bf[h]);
                ldmx4(Bl + off, blf[h]);
            }
            #pragma unroll
            for (int i = 0; i < 4; i++)
                #pragma unroll
                for (int j = 0; j < 4; j++) {
                    const int h = j >> 1, q = j & 1;
                    mma16816(acc[i][j], af[i],  bf[h][2*q],  bf[h][2*q+1]);
                    mma16816(acc[i][j], af[i],  blf[h][2*q], blf[h][2*q+1]);
                    mma16816(acc[i][j], alf[i], bf[h][2*q],  bf[h][2*q+1]);
                }
        }
    };

    LOAD(0, 0);
    LOAD(1, 1);
    #pragma unroll 1
    for (int c = 0; c < NKT; c++) {
        if (c + 2 < NKT) { LOAD(c + 2, (c + 2) % 3); cp_wait<2>(); }
        else if (c + 1 < NKT) { cp_wait<1>(); }
        else { cp_wait<0>(); }
        __syncthreads();
        COMPUTE(c % 3);
        __syncthreads();
    }

    #pragma unroll
    for (int i = 0; i < 4; i++) {
        const int r = row0 + wm + 16 * i + (lane >> 2);
        #pragma unroll
        for (int j = 0; j < 4; j++) {
            const int cc = col0 + wn + 8 * j + (lane & 3) * 2;
            *(float2*)(C + (size_t)r * N + cc) =
                make_float2(acc[i][j][0], acc[i][j][1]);
            *(float2*)(C + (size_t)(r + 8) * N + cc) =
                make_float2(acc[i][j][2], acc[i][j][3]);
        }
    }
}

// ---------------------------------------------------------------------------
// RoPE + head split + transpose (unchanged, passing)
// ---------------------------------------------------------------------------
__global__ __launch_bounds__(256) void rope_kernel(
    const float* __restrict__ qkv,
    const float* __restrict__ cosp, const float* __restrict__ sinp,
    float* __restrict__ gq, float* __restrict__ gk, float* __restrict__ gv)
{
    int idx = blockIdx.x * blockDim.x + threadIdx.x;
    int j = idx & 31;
    int h = (idx >> 5) & (Hq - 1);
    int s = (idx >> 9) & (Sq - 1);
    int b = idx >> 20;
    if (b >= Bq) return;

    const size_t src = ((size_t)(b * Sq + s)) * (3 * Dq) + h * HDq;
    float q0 = qkv[src + 2*j],          q1 = qkv[src + 2*j + 1];
    float k0 = qkv[src + Dq + 2*j],     k1 = qkv[src + Dq + 2*j + 1];
    float v0 = qkv[src + 2*Dq + 2*j],   v1 = qkv[src + 2*Dq + 2*j + 1];

    float c = cosp[s * 32 + j];
    float sn = sinp[s * 32 + j];

    const size_t dst = (((size_t)(b * Hq + h)) * Sq + s) * HDq;
    gq[dst + j]       = q0 * c  - q1 * sn;
    gq[dst + 32 + j]  = q0 * sn + q1 * c;
    gk[dst + j]       = k0 * c  - k1 * sn;
    gk[dst + 32 + j]  = k0 * sn + k1 * c;
    gv[dst + 2*j]     = v0;
    gv[dst + 2*j + 1] = v1;
}

// ---------------------------------------------------------------------------
// Causal flash attention (unchanged, passing)
// ---------------------------------------------------------------------------
#define AQ 128
#define AK 32

__global__ __launch_bounds__(128) void attn_kernel(
    const float* __restrict__ gq, const float* __restrict__ gk,
    const float* __restrict__ gv, float* __restrict__ gout)
{
    const int b   = blockIdx.z;
    const int h   = blockIdx.y;
    const int q0  = blockIdx.x * AQ;
    const int tid = threadIdx.x;
    const int qi  = q0 + tid;

    __shared__ float Qs[AQ][HDq + 1];
    __shared__ float Ks[AK][HDq];
    __shared__ float Vs[AK][HDq];

    const size_t head_base = ((size_t)(b * Hq + h)) * Sq * HDq;
    const float* qptr = gq + head_base;
    const float* kptr = gk + head_base;
    const float* vptr = gv + head_base;

    for (int i = tid; i < AQ * (HDq / 4); i += 128) {
        int r  = i / (HDq / 4);
        int c4 = i % (HDq / 4);
        float4 v = *(const float4*)(qptr + (size_t)(q0 + r) * HDq + c4 * 4);
        Qs[r][c4*4+0] = v.x; Qs[r][c4*4+1] = v.y;
        Qs[r][c4*4+2] = v.z; Qs[r][c4*4+3] = v.w;
    }
    __syncthreads();

    const float sc = 0.125f * 1.4426950408889634f;
    float q[HDq];
    #pragma unroll
    for (int d = 0; d < HDq; d++) q[d] = Qs[tid][d] * sc;

    float m = -1e30f, l = 0.f;
    float acc[HDq];
    #pragma unroll
    for (int d = 0; d < HDq; d++) acc[d] = 0.f;

    const int ntiles = (q0 + AQ) / AK;
    for (int t = 0; t < ntiles; t++) {
        const int k0 = t * AK;
        __syncthreads();
        for (int i = tid; i < AK * (HDq / 4); i += 128) {
            int r  = i / (HDq / 4);
            int c4 = i % (HDq / 4);
            *(float4*)(&Ks[r][c4*4]) =
                *(const float4*)(kptr + (size_t)(k0 + r) * HDq + c4 * 4);
            *(float4*)(&Vs[r][c4*4]) =
                *(const float4*)(vptr + (size_t)(k0 + r) * HDq + c4 * 4);
        }
        __syncthreads();

        if (k0 > qi) continue;

        float s[AK];
        float tmax = -1e30f;
        #pragma unroll
        for (int j = 0; j < AK; j++) {
            float sj = 0.f;
            #pragma unroll
            for (int d = 0; d < HDq; d++) sj += q[d] * Ks[j][d];
            sj = (k0 + j <= qi) ? sj : -1e30f;
            s[j] = sj;
            tmax = fmaxf(tmax, sj);
        }
        float mnew = fmaxf(m, tmax);
        float corr = exp2f(m - mnew);
        l *= corr;
        #pragma unroll
        for (int d = 0; d < HDq; d++) acc[d] *= corr;
        #pragma unroll
        for (int j = 0; j < AK; j++) {
            float p = exp2f(s[j] - mnew);
            l += p;
            #pragma unroll
            for (int d = 0; d < HDq; d++) acc[d] += p * Vs[j][d];
        }
        m = mnew;
    }

    const float inv = 1.f / l;
    float* optr = gout + ((size_t)b * Sq + qi) * Dq + h * HDq;
    #pragma unroll
    for (int d = 0; d < HDq; d += 4) {
        float4 v = make_float4(acc[d]*inv, acc[d+1]*inv, acc[d+2]*inv, acc[d+3]*inv);
        *(float4*)(optr + d) = v;
    }
}

// ---------------------------------------------------------------------------
// Launch
// ---------------------------------------------------------------------------
extern "C" void kernel_launch(void* const* d_in, const int* in_sizes, int n_in,
                              void* d_out, int out_size)
{
    const float* x    = (const float*)d_in[0];
    const float* cosp = (const float*)d_in[1];
    const float* sinp = (const float*)d_in[2];
    // d_in[3] = mask: causal -1e9 — handled analytically, never read.
    const float* Wqkv = (const float*)d_in[4];
    const float* Wout = (const float*)d_in[5];
    float* out = (float*)d_out;

    float *p_qkv, *p_q, *p_k, *p_v, *p_attn;
    cudaGetSymbolAddress((void**)&p_qkv,  g_qkv);
    cudaGetSymbolAddress((void**)&p_q,    g_q);
    cudaGetSymbolAddress((void**)&p_k,    g_k);
    cudaGetSymbolAddress((void**)&p_v,    g_v);
    cudaGetSymbolAddress((void**)&p_attn, g_attn);
    __nv_bfloat16 *p_xhi, *p_xlo, *p_w1hi, *p_w1lo, *p_w2hi, *p_w2lo, *p_ahi, *p_alo;
    cudaGetSymbolAddress((void**)&p_xhi,  g_xhi);
    cudaGetSymbolAddress((void**)&p_xlo,  g_xlo);
    cudaGetSymbolAddress((void**)&p_w1hi, g_w1hi);
    cudaGetSymbolAddress((void**)&p_w1lo, g_w1lo);
    cudaGetSymbolAddress((void**)&p_w2hi, g_w2hi);
    cudaGetSymbolAddress((void**)&p_w2lo, g_w2lo);
    cudaGetSymbolAddress((void**)&p_ahi,  g_ahi);
    cudaGetSymbolAddress((void**)&p_alo,  g_alo);

    cudaFuncSetAttribute(gemm_mma, cudaFuncAttributeMaxDynamicSharedMemorySize,
                         GEMM_SMEM);

    // 0) Split/transpose conversions
    {
        int n4 = Mrows * Kdim / 4;
        split_kernel<<<(n4 + 255) / 256, 256>>>(x, p_xhi, p_xlo, n4);
        dim3 blk(32, 8);
        transpose_split_kernel<<<dim3(3 * Dq / 32, Kdim / 32), blk>>>(Wqkv, p_w1hi, p_w1lo, Kdim, 3 * Dq);
        transpose_split_kernel<<<dim3(Dq / 32, Kdim / 32), blk>>>(Wout, p_w2hi, p_w2lo, Kdim, Dq);
    }
    // 1) QKV projection (mma.sync): [8192,1024] @ [1024,3072]
    {
        dim3 grid(3 * Dq / 128, Mrows / 128);
        gemm_mma<<<grid, 256, GEMM_SMEM>>>(p_xhi, p_xlo, p_w1hi, p_w1lo, p_qkv, 3 * Dq);
    }
    // 2) RoPE + head transpose
    {
        int total = Bq * Hq * Sq * 32;
        rope_kernel<<<total / 256, 256>>>(p_qkv, cosp, sinp, p_q, p_k, p_v);
    }
    // 3) Causal flash attention
    {
        dim3 grid(Sq / AQ, Hq, Bq);
        attn_kernel<<<grid, 128>>>(p_q, p_k, p_v, p_attn);
    }
    // 4) Output projection (mma.sync): [8192,1024] @ [1024,1024]
    {
        int n4 = Mrows * Dq / 4;
        split_kernel<<<(n4 + 255) / 256, 256>>>(p_attn, p_ahi, p_alo, n4);
        dim3 grid(Dq / 128, Mrows / 128);
        gemm_mma<<<grid, 256, GEMM_SMEM>>>(p_ahi, p_alo, p_w2hi, p_w2lo, out, Dq);
    }
}

// round 4
// speedup vs baseline: 3.7708x; 2.7080x over previous
#include <cuda_runtime.h>
#include <cuda_bf16.h>
#include <math.h>
#include <cstdint>

// Problem shape (fixed by the dataset)
#define Bq  4
#define Sq  2048
#define Dq  1024
#define Hq  16
#define HDq 64
#define Mrows (Bq*Sq)          // 8192
#define Kdim 1024

// ---------------------------------------------------------------------------
// Scratch (device globals: allocation-free per harness rules)
// ---------------------------------------------------------------------------
__device__ float g_qkv [(size_t)Mrows * 3 * Dq];     // 8192 x 3072
__device__ float g_attn[(size_t)Mrows * Dq];         // [b,s,D]

// split-bf16 operands for GEMMs
__device__ __nv_bfloat16 g_xhi [(size_t)Mrows * Kdim];
__device__ __nv_bfloat16 g_xlo [(size_t)Mrows * Kdim];
__device__ __nv_bfloat16 g_w1hi[(size_t)3 * Dq * Kdim];
__device__ __nv_bfloat16 g_w1lo[(size_t)3 * Dq * Kdim];
__device__ __nv_bfloat16 g_w2hi[(size_t)Dq * Kdim];
__device__ __nv_bfloat16 g_w2lo[(size_t)Dq * Kdim];
__device__ __nv_bfloat16 g_ahi [(size_t)Mrows * Kdim];
__device__ __nv_bfloat16 g_alo [(size_t)Mrows * Kdim];

// split-bf16 q/k/v in [b,h,s,hd] layout (rope output)
#define QKV_ELEMS ((size_t)Bq*Hq*Sq*HDq)
__device__ __nv_bfloat16 g_qh[QKV_ELEMS];
__device__ __nv_bfloat16 g_ql[QKV_ELEMS];
__device__ __nv_bfloat16 g_kh[QKV_ELEMS];
__device__ __nv_bfloat16 g_kl[QKV_ELEMS];
__device__ __nv_bfloat16 g_vh[QKV_ELEMS];
__device__ __nv_bfloat16 g_vl[QKV_ELEMS];

// ---------------------------------------------------------------------------
// PTX helpers (plain sm_80-era features only; toolchain targets sm_103 w/o 'a')
// ---------------------------------------------------------------------------
__device__ __forceinline__ uint32_t smem_u32(const void* p) {
    uint32_t a;
    asm("{ .reg .u64 t; cvta.to.shared.u64 t, %1; cvt.u32.u64 %0, t; }"
        : "=r"(a) : "l"(p));
    return a;
}
__device__ __forceinline__ void cp_async16(uint32_t s, const void* g) {
    asm volatile("cp.async.cg.shared.global [%0], [%1], 16;" :: "r"(s), "l"(g));
}
__device__ __forceinline__ void cp_commit() {
    asm volatile("cp.async.commit_group;" ::: "memory");
}
template<int N> __device__ __forceinline__ void cp_wait() {
    asm volatile("cp.async.wait_group %0;" :: "n"(N) : "memory");
}
__device__ __forceinline__ void ldmx4(uint32_t addr, uint32_t* r) {
    asm volatile("ldmatrix.sync.aligned.m8n8.x4.shared.b16 {%0,%1,%2,%3}, [%4];"
        : "=r"(r[0]), "=r"(r[1]), "=r"(r[2]), "=r"(r[3]) : "r"(addr));
}
__device__ __forceinline__ void ldmx4t(uint32_t addr, uint32_t* r) {
    asm volatile("ldmatrix.sync.aligned.m8n8.x4.trans.shared.b16 {%0,%1,%2,%3}, [%4];"
        : "=r"(r[0]), "=r"(r[1]), "=r"(r[2]), "=r"(r[3]) : "r"(addr));
}
__device__ __forceinline__ void mma16816(float* d, const uint32_t* a,
                                         uint32_t b0, uint32_t b1) {
    asm volatile(
        "mma.sync.aligned.m16n8k16.row.col.f32.bf16.bf16.f32 "
        "{%0,%1,%2,%3}, {%4,%5,%6,%7}, {%8,%9}, {%0,%1,%2,%3};"
        : "+f"(d[0]), "+f"(d[1]), "+f"(d[2]), "+f"(d[3])
        : "r"(a[0]), "r"(a[1]), "r"(a[2]), "r"(a[3]), "r"(b0), "r"(b1));
}
// pack two fp32 into bf16x2 hi-part; lo-part (residual) via out-param
__device__ __forceinline__ uint32_t packsplit(float x0, float x1, uint32_t& lo) {
    __nv_bfloat16 h0 = __float2bfloat16(x0), h1 = __float2bfloat16(x1);
    float r0 = x0 - __bfloat162float(h0), r1 = x1 - __bfloat162float(h1);
    __nv_bfloat16 l0 = __float2bfloat16(r0), l1 = __float2bfloat16(r1);
    lo = (uint32_t)__bfloat16_as_ushort(l0) | ((uint32_t)__bfloat16_as_ushort(l1) << 16);
    return (uint32_t)__bfloat16_as_ushort(h0) | ((uint32_t)__bfloat16_as_ushort(h1) << 16);
}

// ---------------------------------------------------------------------------
// Split-bf16 conversion: x -> (hi, lo)
// ---------------------------------------------------------------------------
__global__ __launch_bounds__(256) void split_kernel(
    const float* __restrict__ x, __nv_bfloat16* __restrict__ hi,
    __nv_bfloat16* __restrict__ lo, int n4)
{
    int i = blockIdx.x * blockDim.x + threadIdx.x;
    if (i >= n4) return;
    float4 v = ((const float4*)x)[i];
    uint32_t l01, l23;
    uint32_t h01 = packsplit(v.x, v.y, l01);
    uint32_t h23 = packsplit(v.z, v.w, l23);
    ((uint2*)hi)[i] = make_uint2(h01, h23);
    ((uint2*)lo)[i] = make_uint2(l01, l23);
}

// ---------------------------------------------------------------------------
// Transpose + split: W[K,N] fp32 -> T[N,K] bf16 hi/lo
// ---------------------------------------------------------------------------
__global__ __launch_bounds__(256) void transpose_split_kernel(
    const float* __restrict__ W, __nv_bfloat16* __restrict__ Thi,
    __nv_bfloat16* __restrict__ Tlo, int K, int N)
{
    __shared__ float t[32][33];
    int n0 = blockIdx.x * 32, k0 = blockIdx.y * 32;
    int tx = threadIdx.x, ty = threadIdx.y;   // (32, 8)
    #pragma unroll
    for (int i = 0; i < 32; i += 8)
        t[ty + i][tx] = W[(size_t)(k0 + ty + i) * N + n0 + tx];
    __syncthreads();
    #pragma unroll
    for (int i = 0; i < 32; i += 8) {
        float v = t[tx][ty + i];
        __nv_bfloat16 h = __float2bfloat16(v);
        size_t o = (size_t)(n0 + ty + i) * K + k0 + tx;
        Thi[o] = h;
        Tlo[o] = __float2bfloat16(v - __bfloat162float(h));
    }
}

// ---------------------------------------------------------------------------
// mma.sync split-bf16 GEMM (unchanged, verified): C = A @ B^T
// ---------------------------------------------------------------------------
#define NKT      (Kdim / 32)
#define TILE8K   8192
#define STAGE_B  (4 * TILE8K)
#define GEMM_SMEM (3 * STAGE_B)

__global__ __launch_bounds__(256, 1) void gemm_mma(
    const __nv_bfloat16* __restrict__ Ahi, const __nv_bfloat16* __restrict__ Alo,
    const __nv_bfloat16* __restrict__ Bhi, const __nv_bfloat16* __restrict__ Blo,
    float* __restrict__ C, int N)
{
    extern __shared__ char sm[];
    const uint32_t sbase = smem_u32(sm);
    const int tid = threadIdx.x, wid = tid >> 5, lane = tid & 31;
    const int row0 = blockIdx.y * 128, col0 = blockIdx.x * 128;
    const int wm = (wid >> 2) * 64, wn = (wid & 3) * 32;

    const __nv_bfloat16* gsrc[4] = {
        Ahi + (size_t)row0 * Kdim, Alo + (size_t)row0 * Kdim,
        Bhi + (size_t)col0 * Kdim, Blo + (size_t)col0 * Kdim };

    float acc[4][4][4];
    #pragma unroll
    for (int i = 0; i < 4; i++)
        #pragma unroll
        for (int j = 0; j < 4; j++)
            #pragma unroll
            for (int r = 0; r < 4; r++) acc[i][j][r] = 0.f;

    const int lrow = tid >> 2;
    const int lch  = tid & 3;

    auto LOAD = [&](int ct, int st) {
        const int kk = ct * 32;
        const uint32_t sb = sbase + st * STAGE_B;
        #pragma unroll
        for (int t = 0; t < 4; t++) {
            #pragma unroll
            for (int rep = 0; rep < 2; rep++) {
                int row = lrow + rep * 64;
                uint32_t so = sb + t * TILE8K + row * 64
                            + ((uint32_t)(lch ^ ((row >> 1) & 3)) << 4);
                cp_async16(so, gsrc[t] + (size_t)row * Kdim + kk + lch * 8);
            }
        }
        cp_commit();
    };

    auto COMPUTE = [&](int st) {
        const uint32_t Ah = sbase + st * STAGE_B;
        const uint32_t Al = Ah + TILE8K, Bh = Ah + 2 * TILE8K, Bl = Ah + 3 * TILE8K;
        const int g = lane >> 3, lr = lane & 7;
        #pragma unroll
        for (int s = 0; s < 2; s++) {
            uint32_t af[4][4], alf[4][4], bf[2][4], blf[2][4];
            #pragma unroll
            for (int i = 0; i < 4; i++) {
                int row = wm + 16 * i + (g & 1) * 8 + lr;
                int ch  = 2 * s + (g >> 1);
                uint32_t off = (uint32_t)(row * 64 + ((ch ^ ((row >> 1) & 3)) << 4));
                ldmx4(Ah + off, af[i]);
                ldmx4(Al + off, alf[i]);
            }
            #pragma unroll
            for (int h = 0; h < 2; h++) {
                int row = wn + 16 * h + (g >> 1) * 8 + lr;
                int ch  = 2 * s + (g & 1);
                uint32_t off = (uint32_t)(row * 64 + ((ch ^ ((row >> 1) & 3)) << 4));
                ldmx4(Bh + off, bf[h]);
                ldmx4(Bl + off, blf[h]);
            }
            #pragma unroll
            for (int i = 0; i < 4; i++)
                #pragma unroll
                for (int j = 0; j < 4; j++) {
                    const int h = j >> 1, q = j & 1;
                    mma16816(acc[i][j], af[i],  bf[h][2*q],  bf[h][2*q+1]);
                    mma16816(acc[i][j], af[i],  blf[h][2*q], blf[h][2*q+1]);
                    mma16816(acc[i][j], alf[i], bf[h][2*q],  bf[h][2*q+1]);
                }
        }
    };

    LOAD(0, 0);
    LOAD(1, 1);
    #pragma unroll 1
    for (int c = 0; c < NKT; c++) {
        if (c + 2 < NKT) { LOAD(c + 2, (c + 2) % 3); cp_wait<2>(); }
        else if (c + 1 < NKT) { cp_wait<1>(); }
        else { cp_wait<0>(); }
        __syncthreads();
        COMPUTE(c % 3);
        __syncthreads();
    }

    #pragma unroll
    for (int i = 0; i < 4; i++) {
        const int r = row0 + wm + 16 * i + (lane >> 2);
        #pragma unroll
        for (int j = 0; j < 4; j++) {
            const int cc = col0 + wn + 8 * j + (lane & 3) * 2;
            *(float2*)(C + (size_t)r * N + cc) =
                make_float2(acc[i][j][0], acc[i][j][1]);
            *(float2*)(C + (size_t)(r + 8) * N + cc) =
                make_float2(acc[i][j][2], acc[i][j][3]);
        }
    }
}

// ---------------------------------------------------------------------------
// RoPE + head split + split-bf16 conversion: qkv[b,s,3D] -> q/k/v hi/lo [b,h,s,hd]
// Q is pre-scaled by 1/sqrt(hd) * log2(e) (softmax runs in exp2 domain).
// ---------------------------------------------------------------------------
__global__ __launch_bounds__(256) void rope_kernel(
    const float* __restrict__ qkv,
    const float* __restrict__ cosp, const float* __restrict__ sinp,
    __nv_bfloat16* __restrict__ qh, __nv_bfloat16* __restrict__ ql,
    __nv_bfloat16* __restrict__ kh, __nv_bfloat16* __restrict__ kl,
    __nv_bfloat16* __restrict__ vh, __nv_bfloat16* __restrict__ vl)
{
    int idx = blockIdx.x * blockDim.x + threadIdx.x;
    int j = idx & 31;
    int h = (idx >> 5) & (Hq - 1);
    int s = (idx >> 9) & (Sq - 1);
    int b = idx >> 20;
    if (b >= Bq) return;

    const size_t src = ((size_t)(b * Sq + s)) * (3 * Dq) + h * HDq;
    float q0 = qkv[src + 2*j],          q1 = qkv[src + 2*j + 1];
    float k0 = qkv[src + Dq + 2*j],     k1 = qkv[src + Dq + 2*j + 1];
    float v0 = qkv[src + 2*Dq + 2*j],   v1 = qkv[src + 2*Dq + 2*j + 1];

    float c = cosp[s * 32 + j];
    float sn = sinp[s * 32 + j];
    const float sc = 0.125f * 1.4426950408889634f;   // 1/sqrt(64)*log2(e)

    float qa = (q0 * c  - q1 * sn) * sc;
    float qb = (q0 * sn + q1 * c) * sc;
    float ka = k0 * c  - k1 * sn;
    float kb = k0 * sn + k1 * c;

    const size_t dst = (((size_t)(b * Hq + h)) * Sq + s) * HDq;
    #define WSPLIT(arrh, arrl, off, val) do { \
        __nv_bfloat16 _h = __float2bfloat16(val); \
        arrh[dst + (off)] = _h; \
        arrl[dst + (off)] = __float2bfloat16((val) - __bfloat162float(_h)); \
    } while (0)
    WSPLIT(qh, ql, j,        qa);
    WSPLIT(qh, ql, 32 + j,   qb);
    WSPLIT(kh, kl, j,        ka);
    WSPLIT(kh, kl, 32 + j,   kb);
    WSPLIT(vh, vl, 2*j,      v0);
    WSPLIT(vh, vl, 2*j + 1,  v1);
    #undef WSPLIT
}

// ---------------------------------------------------------------------------
// Tensor-core causal flash attention (FA2-style, split-bf16 everywhere).
// CTA = 128 queries, 8 warps x 16 q. Key tile = 64, double-buffered cp.async.
// SMEM: Qhi/Qlo [128][64] + 2 x {Khi,Klo,Vhi,Vlo}[64][64]  = 96 KB.
// Row = 64 bf16 = 128B, swizzle: ch' = ch ^ (row&7)  (ch = 16B chunk, 0..7).
// ---------------------------------------------------------------------------
#define AKT 64
#define AQT 128
#define ATT_SMEM 98304

__device__ __forceinline__ uint32_t sw_off(int row, int ch) {
    return (uint32_t)(row * 128 + ((ch ^ (row & 7)) << 4));
}

__global__ __launch_bounds__(256, 1) void attn_mma(
    const __nv_bfloat16* __restrict__ gqh, const __nv_bfloat16* __restrict__ gql,
    const __nv_bfloat16* __restrict__ gkh, const __nv_bfloat16* __restrict__ gkl,
    const __nv_bfloat16* __restrict__ gvh, const __nv_bfloat16* __restrict__ gvl,
    float* __restrict__ gout)
{
    extern __shared__ char sm[];
    const uint32_t sbase = smem_u32(sm);
    const uint32_t QH = sbase, QL = sbase + 16384;
    const int tid = threadIdx.x, wid = tid >> 5, lane = tid & 31;
    const int g = lane >> 3, lr = lane & 7;

    const int qb = (gridDim.x - 1) - blockIdx.x;     // heavy tiles first
    const int h  = blockIdx.y, b = blockIdx.z;
    const int q_base = qb * AQT;
    const int ntile = q_base / AKT + 2;

    const size_t hb = (((size_t)(b * Hq + h)) * Sq) * HDq;
    const __nv_bfloat16* kvsrc[4] = {gkh + hb, gkl + hb, gvh + hb, gvl + hb};

    // ---- loaders -----------------------------------------------------------
    auto load_q = [&]() {
        #pragma unroll
        for (int it = 0; it < 8; it++) {
            int i = tid + it * 256;              // 2048 chunks
            int arr = i >> 10, rem = i & 1023;
            int row = rem >> 3, ch = rem & 7;
            const __nv_bfloat16* src = (arr ? gql : gqh) + hb
                                     + (size_t)(q_base + row) * HDq + ch * 8;
            cp_async16(sbase + arr * 16384 + sw_off(row, ch), src);
        }
    };
    auto load_kv = [&](int t, int bi) {
        const int k0 = t * AKT;
        const uint32_t sb = sbase + 32768 + bi * 32768;
        #pragma unroll
        for (int it = 0; it < 8; it++) {
            int i = tid + it * 256;              // 2048 chunks
            int arr = i >> 9, rem = i & 511;
            int row = rem >> 3, ch = rem & 7;
            cp_async16(sb + arr * 8192 + sw_off(row, ch),
                       kvsrc[arr] + (size_t)(k0 + row) * HDq + ch * 8);
        }
    };

    // ---- prologue ----------------------------------------------------------
    load_q(); load_kv(0, 0); cp_commit();
    load_kv(1, 1); cp_commit();
    cp_wait<1>();
    __syncthreads();

    // Q fragments (persist in registers): 4 k16-steps, hi+lo
    uint32_t qfh[4][4], qfl[4][4];
    #pragma unroll
    for (int s4 = 0; s4 < 4; s4++) {
        int row = wid * 16 + (g & 1) * 8 + lr;
        int ch  = 2 * s4 + (g >> 1);
        ldmx4(QH + sw_off(row, ch), qfh[s4]);
        ldmx4(QL + sw_off(row, ch), qfl[s4]);
    }

    float m0 = -1e30f, m1 = -1e30f, l0 = 0.f, l1 = 0.f;
    float o[8][4];
    #pragma unroll
    for (int j = 0; j < 8; j++)
        #pragma unroll
        for (int e = 0; e < 4; e++) o[j][e] = 0.f;

    const int wq = q_base + wid * 16;            // warp's first query row
    const int qg0 = wq + (lane >> 2);            // row for c0,c1 (c2,c3 = +8)

    // ---- main loop ----------------------------------------------------------
    for (int t = 0; t < ntile; t++) {
        const int k0 = t * AKT;
        const uint32_t BUF = sbase + 32768 + (t & 1) * 32768;
        const uint32_t KH = BUF, KL = BUF + 8192, VH = BUF + 16384, VL = BUF + 24576;

        if (k0 <= wq + 15) {                     // warp has unmasked rows here
            // ---- scores: S = Q K^T (split-3) ----
            float s[8][4];
            #pragma unroll
            for (int nt = 0; nt < 8; nt++)
                #pragma unroll
                for (int e = 0; e < 4; e++) s[nt][e] = 0.f;

            #pragma unroll
            for (int kh4 = 0; kh4 < 4; kh4++) {
                #pragma unroll
                for (int s4 = 0; s4 < 4; s4++) {
                    int row = 16 * kh4 + (g >> 1) * 8 + lr;
                    int ch  = 2 * s4 + (g & 1);
                    uint32_t kf[4], lf[4];
                    ldmx4(KH + sw_off(row, ch), kf);
                    ldmx4(KL + sw_off(row, ch), lf);
                    mma16816(s[2*kh4],   qfh[s4], kf[0], kf[1]);
                    mma16816(s[2*kh4],   qfh[s4], lf[0], lf[1]);
                    mma16816(s[2*kh4],   qfl[s4], kf[0], kf[1]);
                    mma16816(s[2*kh4+1], qfh[s4], kf[2], kf[3]);
                    mma16816(s[2*kh4+1], qfh[s4], lf[2], lf[3]);
                    mma16816(s[2*kh4+1], qfl[s4], kf[2], kf[3]);
                }
            }

            // ---- causal mask (diagonal tiles only) ----
            if (k0 + AKT - 1 > wq) {
                #pragma unroll
                for (int nt = 0; nt < 8; nt++) {
                    int kg = k0 + nt * 8 + (lane & 3) * 2;
                    if (kg     > qg0)     s[nt][0] = -1e30f;
                    if (kg + 1 > qg0)     s[nt][1] = -1e30f;
                    if (kg     > qg0 + 8) s[nt][2] = -1e30f;
                    if (kg + 1 > qg0 + 8) s[nt][3] = -1e30f;
                }
            }

            // ---- online softmax (exp2 domain; scale pre-folded into Q) ----
            float t0 = -1e30f, t1 = -1e30f;
            #pragma unroll
            for (int nt = 0; nt < 8; nt++) {
                t0 = fmaxf(t0, fmaxf(s[nt][0], s[nt][1]));
                t1 = fmaxf(t1, fmaxf(s[nt][2], s[nt][3]));
            }
            t0 = fmaxf(t0, __shfl_xor_sync(0xffffffffu, t0, 1));
            t0 = fmaxf(t0, __shfl_xor_sync(0xffffffffu, t0, 2));
            t1 = fmaxf(t1, __shfl_xor_sync(0xffffffffu, t1, 1));
            t1 = fmaxf(t1, __shfl_xor_sync(0xffffffffu, t1, 2));
            float mn0 = fmaxf(m0, t0), mn1 = fmaxf(m1, t1);
            float c0 = exp2f(m0 - mn0), c1 = exp2f(m1 - mn1);
            m0 = mn0; m1 = mn1;
            l0 *= c0; l1 *= c1;
            #pragma unroll
            for (int j = 0; j < 8; j++) {
                o[j][0] *= c0; o[j][1] *= c0; o[j][2] *= c1; o[j][3] *= c1;
            }
            #pragma unroll
            for (int nt = 0; nt < 8; nt++) {
                s[nt][0] = exp2f(s[nt][0] - mn0);
                s[nt][1] = exp2f(s[nt][1] - mn0);
                s[nt][2] = exp2f(s[nt][2] - mn1);
                s[nt][3] = exp2f(s[nt][3] - mn1);
                l0 += s[nt][0] + s[nt][1];
                l1 += s[nt][2] + s[nt][3];
            }

            // ---- O += P V (split-3), V via ldmatrix.trans ----
            #pragma unroll
            for (int kp = 0; kp < 4; kp++) {
                uint32_t aph[4], apl[4];
                aph[0] = packsplit(s[2*kp][0],   s[2*kp][1],   apl[0]);
                aph[1] = packsplit(s[2*kp][2],   s[2*kp][3],   apl[1]);
                aph[2] = packsplit(s[2*kp+1][0], s[2*kp+1][1], apl[2]);
                aph[3] = packsplit(s[2*kp+1][2], s[2*kp+1][3], apl[3]);
                #pragma unroll
                for (int j2 = 0; j2 < 4; j2++) {
                    int row = kp * 16 + (g & 1) * 8 + lr;
                    int ch  = 2 * j2 + (g >> 1);
                    uint32_t vf[4], wf[4];
                    ldmx4t(VH + sw_off(row, ch), vf);
                    ldmx4t(VL + sw_off(row, ch), wf);
                    mma16816(o[2*j2],   aph, vf[0], vf[1]);
                    mma16816(o[2*j2],   aph, wf[0], wf[1]);
                    mma16816(o[2*j2],   apl, vf[0], vf[1]);
                    mma16816(o[2*j2+1], aph, vf[2], vf[3]);
                    mma16816(o[2*j2+1], aph, wf[2], wf[3]);
                    mma16816(o[2*j2+1], apl, vf[2], vf[3]);
                }
            }
        }

        __syncthreads();                         // compute done before refill
        if (t + 2 < ntile) {
            load_kv(t + 2, t & 1); cp_commit(); cp_wait<1>();
        } else if (t + 1 < ntile) {
            cp_wait<0>();
        }
        __syncthreads();
    }

    // ---- normalize + write [b,s,D] ----
    float ls0 = l0 + __shfl_xor_sync(0xffffffffu, l0, 1);
    ls0 += __shfl_xor_sync(0xffffffffu, ls0, 2);
    float ls1 = l1 + __shfl_xor_sync(0xffffffffu, l1, 1);
    ls1 += __shfl_xor_sync(0xffffffffu, ls1, 2);
    const float inv0 = 1.f / ls0, inv1 = 1.f / ls1;

    float* out0 = gout + ((size_t)b * Sq + qg0) * Dq + h * HDq;
    float* out1 = gout + ((size_t)b * Sq + qg0 + 8) * Dq + h * HDq;
    #pragma unroll
    for (int j = 0; j < 8; j++) {
        int cc = j * 8 + (lane & 3) * 2;
        *(float2*)(out0 + cc) = make_float2(o[j][0] * inv0, o[j][1] * inv0);
        *(float2*)(out1 + cc) = make_float2(o[j][2] * inv1, o[j][3] * inv1);
    }
}

// ---------------------------------------------------------------------------
// Launch
// ---------------------------------------------------------------------------
extern "C" void kernel_launch(void* const* d_in, const int* in_sizes, int n_in,
                              void* d_out, int out_size)
{
    const float* x    = (const float*)d_in[0];
    const float* cosp = (const float*)d_in[1];
    const float* sinp = (const float*)d_in[2];
    // d_in[3] = mask: causal -1e9 — handled analytically, never read.
    const float* Wqkv = (const float*)d_in[4];
    const float* Wout = (const float*)d_in[5];
    float* out = (float*)d_out;

    float *p_qkv, *p_attn;
    cudaGetSymbolAddress((void**)&p_qkv,  g_qkv);
    cudaGetSymbolAddress((void**)&p_attn, g_attn);
    __nv_bfloat16 *p_xhi, *p_xlo, *p_w1hi, *p_w1lo, *p_w2hi, *p_w2lo, *p_ahi, *p_alo;
    __nv_bfloat16 *p_qh, *p_ql, *p_kh, *p_kl, *p_vh, *p_vl;
    cudaGetSymbolAddress((void**)&p_xhi,  g_xhi);
    cudaGetSymbolAddress((void**)&p_xlo,  g_xlo);
    cudaGetSymbolAddress((void**)&p_w1hi, g_w1hi);
    cudaGetSymbolAddress((void**)&p_w1lo, g_w1lo);
    cudaGetSymbolAddress((void**)&p_w2hi, g_w2hi);
    cudaGetSymbolAddress((void**)&p_w2lo, g_w2lo);
    cudaGetSymbolAddress((void**)&p_ahi,  g_ahi);
    cudaGetSymbolAddress((void**)&p_alo,  g_alo);
    cudaGetSymbolAddress((void**)&p_qh,   g_qh);
    cudaGetSymbolAddress((void**)&p_ql,   g_ql);
    cudaGetSymbolAddress((void**)&p_kh,   g_kh);
    cudaGetSymbolAddress((void**)&p_kl,   g_kl);
    cudaGetSymbolAddress((void**)&p_vh,   g_vh);
    cudaGetSymbolAddress((void**)&p_vl,   g_vl);

    cudaFuncSetAttribute(gemm_mma, cudaFuncAttributeMaxDynamicSharedMemorySize,
                         GEMM_SMEM);
    cudaFuncSetAttribute(attn_mma, cudaFuncAttributeMaxDynamicSharedMemorySize,
                         ATT_SMEM);

    // 0) Split/transpose conversions
    {
        int n4 = Mrows * Kdim / 4;
        split_kernel<<<(n4 + 255) / 256, 256>>>(x, p_xhi, p_xlo, n4);
        dim3 blk(32, 8);
        transpose_split_kernel<<<dim3(3 * Dq / 32, Kdim / 32), blk>>>(Wqkv, p_w1hi, p_w1lo, Kdim, 3 * Dq);
        transpose_split_kernel<<<dim3(Dq / 32, Kdim / 32), blk>>>(Wout, p_w2hi, p_w2lo, Kdim, Dq);
    }
    // 1) QKV projection (mma.sync)
    {
        dim3 grid(3 * Dq / 128, Mrows / 128);
        gemm_mma<<<grid, 256, GEMM_SMEM>>>(p_xhi, p_xlo, p_w1hi, p_w1lo, p_qkv, 3 * Dq);
    }
    // 2) RoPE + head transpose + split-bf16
    {
        int total = Bq * Hq * Sq * 32;
        rope_kernel<<<total / 256, 256>>>(p_qkv, cosp, sinp,
                                          p_qh, p_ql, p_kh, p_kl, p_vh, p_vl);
    }
    // 3) Tensor-core causal flash attention
    {
        dim3 grid(Sq / AQT, Hq, Bq);
        attn_mma<<<grid, 256, ATT_SMEM>>>(p_qh, p_ql, p_kh, p_kl, p_vh, p_vl, p_attn);
    }
    // 4) Output projection (mma.sync)
    {
        int n4 = Mrows * Dq / 4;
        split_kernel<<<(n4 + 255) / 256, 256>>>(p_attn, p_ahi, p_alo, n4);
        dim3 grid(Dq / 128, Mrows / 128);
        gemm_mma<<<grid, 256, GEMM_SMEM>>>(p_ahi, p_alo, p_w2hi, p_w2lo, out, Dq);
    }
}